// round 14
// baseline (speedup 1.0000x reference)
#include <cuda_runtime.h>

#define NB 16
#define NBG 4        // batches per stream-group
#define NGRP 4       // stream groups (NBG*NGRP == NB)
#define NC 8
#define NS 128
#define NSTEPS 10
#define EPSF 1e-6f
#define FULLM 0xFFFFFFFFu
#define NITER 2      // proven sufficient (rel_err 7e-7)
#define SX 0.0005f   // (dt/2)/dx^2
#define SY 0.001f    // dt/dy^2
#define PLANE (NC*NS*NS)          // floats per coefficient set

// device globals (allocation-free rule). NEVER address these from host code:
// the host shadow is a host address and GB300 HMM happily reads it (R12/R13 bug).
static __device__ float g_u [NB*NC*NS*NS];           // ping state [b][c][h][w]
static __device__ float g_ka[(NSTEPS+1)*PLANE];      // alpha-k sets, t = m*dt
static __device__ float g_kb[ NSTEPS   *PLANE];      // beta-k sets,  t = m*dt + dt/2

// streams/events created once at module load (no device allocations involved)
static cudaStream_t g_s[NGRP];
static cudaEvent_t  g_fork, g_pre, g_join[NGRP];
namespace {
struct StreamInit {
    StreamInit() {
        for (int i = 0; i < NGRP; i++)
            cudaStreamCreateWithFlags(&g_s[i], cudaStreamNonBlocking);
        cudaEventCreateWithFlags(&g_fork, cudaEventDisableTiming);
        cudaEventCreateWithFlags(&g_pre,  cudaEventDisableTiming);
        for (int i = 0; i < NGRP; i++)
            cudaEventCreateWithFlags(&g_join[i], cudaEventDisableTiming);
    }
} g_streamInit;
}

// ---------------------------------------------------------------------------
// Coefficient precompute: all 11 alpha sets + 10 beta sets, float4 per thread.
// Bit-identical to the R9 inline computation.
// ---------------------------------------------------------------------------
#define NA4 ((NSTEPS+1)*PLANE/4)
#define NB4 ( NSTEPS   *PLANE/4)
__global__ void kpre(const float* __restrict__ ab, const float* __restrict__ atc,
                     const float* __restrict__ bb, const float* __restrict__ btc)
{
    const int idx = blockIdx.x*blockDim.x + threadIdx.x;
    if (idx < NA4) {
        const int m = idx / (PLANE/4);
        const int r = idx % (PLANE/4);
        const float t = (float)((double)m * 0.001);
        const float4 a = ((const float4*)ab)[r];
        const float4 c = ((const float4*)atc)[r];
        float4 o;
        o.x = fminf(fmaxf(fmaf(c.x, t, a.x), 1e-6f), 10.f) * SX;
        o.y = fminf(fmaxf(fmaf(c.y, t, a.y), 1e-6f), 10.f) * SX;
        o.z = fminf(fmaxf(fmaf(c.z, t, a.z), 1e-6f), 10.f) * SX;
        o.w = fminf(fmaxf(fmaf(c.w, t, a.w), 1e-6f), 10.f) * SX;
        ((float4*)g_ka)[idx] = o;
    } else if (idx < NA4 + NB4) {
        const int id = idx - NA4;
        const int m = id / (PLANE/4);
        const int r = id % (PLANE/4);
        const float t = (float)((double)m * 0.001 + 0.0005);
        const float4 a = ((const float4*)bb)[r];
        const float4 c = ((const float4*)btc)[r];
        float4 o;
        o.x = fminf(fmaxf(fmaf(c.x, t, a.x), 1e-6f), 10.f) * SY;
        o.y = fminf(fmaxf(fmaf(c.y, t, a.y), 1e-6f), 10.f) * SY;
        o.z = fminf(fmaxf(fmaf(c.z, t, a.z), 1e-6f), 10.f) * SY;
        o.w = fminf(fmaxf(fmaf(c.w, t, a.w), 1e-6f), 10.f) * SY;
        ((float4*)g_kb)[id] = o;
    }
}

// ---------------------------------------------------------------------------
// Warp-shuffle Neumann solve (2 iters); warp owns a 128-row, 4 elems/thread.
// Mirror ghosts reproduce the 1+k boundary diagonal exactly.
// ---------------------------------------------------------------------------
static __device__ __forceinline__ void xsolve(float y[4], const float d[4],
                                              const float k[4], int l)
{
    #pragma unroll
    for (int it = 0; it < NITER; it++) {
        float ym1 = __shfl_up_sync(FULLM, y[3], 1);
        float yp1 = __shfl_down_sync(FULLM, y[0], 1);
        if (l == 0)  ym1 = y[0];
        if (l == 31) yp1 = y[3];
        float prev = ym1;
        #pragma unroll
        for (int e = 0; e < 4; e++) {
            float cur = y[e];
            float nxt = (e < 3) ? y[e+1] : yp1;
            float L = 2.f*cur - prev - nxt;
            y[e] = d[e] - fmaf(k[e], L, EPSF*cur);
            prev = cur;
        }
    }
}

// ---------------------------------------------------------------------------
// X-direction kernel. CTA = (b, h); warp c = channel c. `set` selects the
// g_ka coefficient slice IN DEVICE CODE (host must not address g_ka).
// MODE 0: mix(usrc) + X (inline t=0 coeff from ab) -> g_u
// MODE 1: X + mix + X (in place, set ka)           -> g_u
// MODE 2: X (set ka)                               -> uout
// ---------------------------------------------------------------------------
template<int MODE>
__global__ void __launch_bounds__(256) k_x(const float* __restrict__ usrc,
                                           float* __restrict__ uout,
                                           const float* __restrict__ ab,
                                           const float* __restrict__ cm,
                                           int set, int b0)
{
    __shared__ float sm[NC][NS];
    const int tid = threadIdx.x;
    const int c = tid >> 5;
    const int l = tid & 31;
    const int b = b0 + (blockIdx.x >> 7);
    const int h = blockIdx.x & 127;

    const size_t crow = (((size_t)c*NS + h))*NS + 4*l;
    const size_t urow = ((((size_t)b*NC + c)*NS + h))*NS + 4*l;

    float k[4];
    if (MODE == 0) {   // t=0: k = clip(ab)*SX
        const float4 a4 = *(const float4*)(ab + crow);
        k[0] = fminf(fmaxf(a4.x, 1e-6f), 10.f) * SX;
        k[1] = fminf(fmaxf(a4.y, 1e-6f), 10.f) * SX;
        k[2] = fminf(fmaxf(a4.z, 1e-6f), 10.f) * SX;
        k[3] = fminf(fmaxf(a4.w, 1e-6f), 10.f) * SX;
    } else {
        const float* ka = g_ka + (size_t)set*PLANE;    // device-side symbol use
        const float4 k4 = *(const float4*)(ka + crow);
        k[0] = k4.x; k[1] = k4.y; k[2] = k4.z; k[3] = k4.w;
    }

    float cmr[8];
    if (MODE != 2) {
        #pragma unroll
        for (int j = 0; j < 8; j++) cmr[j] = cm[c*8 + j];
    }

    float d[4];
    {
        const float* src = (MODE == 0) ? usrc : (const float*)g_u;
        const float4 v = *(const float4*)(src + urow);
        d[0] = v.x; d[1] = v.y; d[2] = v.z; d[3] = v.w;
    }

    if (MODE == 0) {
        *(float4*)&sm[c][4*l] = make_float4(d[0], d[1], d[2], d[3]);
        __syncthreads();
        float m[4] = {0.f, 0.f, 0.f, 0.f};
        #pragma unroll
        for (int j = 0; j < 8; j++) {
            const float4 v = *(const float4*)&sm[j][4*l];
            m[0] = fmaf(cmr[j], v.x, m[0]);
            m[1] = fmaf(cmr[j], v.y, m[1]);
            m[2] = fmaf(cmr[j], v.z, m[2]);
            m[3] = fmaf(cmr[j], v.w, m[3]);
        }
        float y[4] = {m[0], m[1], m[2], m[3]};
        xsolve(y, m, k, l);
        *(float4*)((float*)g_u + urow) = make_float4(y[0], y[1], y[2], y[3]);
    } else if (MODE == 1) {
        float y[4] = {d[0], d[1], d[2], d[3]};
        xsolve(y, d, k, l);
        *(float4*)&sm[c][4*l] = make_float4(y[0], y[1], y[2], y[3]);
        __syncthreads();
        float m[4] = {0.f, 0.f, 0.f, 0.f};
        #pragma unroll
        for (int j = 0; j < 8; j++) {
            const float4 v = *(const float4*)&sm[j][4*l];
            m[0] = fmaf(cmr[j], v.x, m[0]);
            m[1] = fmaf(cmr[j], v.y, m[1]);
            m[2] = fmaf(cmr[j], v.z, m[2]);
            m[3] = fmaf(cmr[j], v.w, m[3]);
        }
        float y2[4] = {m[0], m[1], m[2], m[3]};
        xsolve(y2, m, k, l);
        *(float4*)((float*)g_u + urow) = make_float4(y2[0], y2[1], y2[2], y2[3]);
    } else {
        float y[4] = {d[0], d[1], d[2], d[3]};
        xsolve(y, d, k, l);
        *(float4*)(uout + urow) = make_float4(y[0], y[1], y[2], y[3]);
    }
}

// ---------------------------------------------------------------------------
// Y-direction kernel. CTA = one (b,c) plane; 1024 threads = 32 warps x 32
// lanes. Warp ww owns h rows 4ww..4ww+3; lane owns float4 in w. All mem ops
// LDG.128/STG.128. Single-buffered 32KB halo smem (<48KB static limit):
// write -> sync -> capture halos -> sync -> update. `set` selects g_kb slice
// in device code. Iter 0 uses d==y; iter 1 reloads d from L1-hot global.
// ---------------------------------------------------------------------------
__global__ void __launch_bounds__(1024, 1) k_y(int set, int b0)
{
    __shared__ float4 sTop[32][32];    // 16 KB
    __shared__ float4 sBot[32][32];    // 16 KB
    const int l  = threadIdx.x & 31;
    const int ww = threadIdx.x >> 5;   // 0..31: segment of 4 h rows
    const int c  = blockIdx.x & 7;
    const int b  = b0 + (blockIdx.x >> 3);
    const int h0 = ww*4;

    float* up = (float*)g_u + ((((size_t)b*NC + c)*NS + h0)*NS) + 4*l;
    const float* kp = g_kb + (size_t)set*PLANE + (((size_t)c*NS + h0)*NS) + 4*l;

    float4 y4[4], k4[4];
    #pragma unroll
    for (int j = 0; j < 4; j++) {
        y4[j] = *(const float4*)(up + j*NS);
        k4[j] = *(const float4*)(kp + j*NS);
    }

    // ---- iteration 0 (d == y) ----
    {
        sTop[ww][l] = y4[0];
        sBot[ww][l] = y4[3];
        __syncthreads();
        float4 prev = (ww == 0)  ? y4[0] : sBot[ww-1][l];
        const float4 ypn = (ww == 31) ? y4[3] : sTop[ww+1][l];
        __syncthreads();   // halo reads done before iter-1 overwrites
        #pragma unroll
        for (int j = 0; j < 4; j++) {
            const float4 cur = y4[j];
            const float4 nxt = (j < 3) ? y4[j+1] : ypn;
            y4[j].x = cur.x - fmaf(k4[j].x, 2.f*cur.x - prev.x - nxt.x, EPSF*cur.x);
            y4[j].y = cur.y - fmaf(k4[j].y, 2.f*cur.y - prev.y - nxt.y, EPSF*cur.y);
            y4[j].z = cur.z - fmaf(k4[j].z, 2.f*cur.z - prev.z - nxt.z, EPSF*cur.z);
            y4[j].w = cur.w - fmaf(k4[j].w, 2.f*cur.w - prev.w - nxt.w, EPSF*cur.w);
            prev = cur;
        }
    }
    // ---- iteration 1 (reload d from global; L1-hot) ----
    {
        sTop[ww][l] = y4[0];
        sBot[ww][l] = y4[3];
        __syncthreads();
        float4 prev = (ww == 0)  ? y4[0] : sBot[ww-1][l];
        const float4 ypn = (ww == 31) ? y4[3] : sTop[ww+1][l];
        #pragma unroll
        for (int j = 0; j < 4; j++) {
            const float4 cur = y4[j];
            const float4 nxt = (j < 3) ? y4[j+1] : ypn;
            const float4 d = *(const float4*)(up + j*NS);
            y4[j].x = d.x - fmaf(k4[j].x, 2.f*cur.x - prev.x - nxt.x, EPSF*cur.x);
            y4[j].y = d.y - fmaf(k4[j].y, 2.f*cur.y - prev.y - nxt.y, EPSF*cur.y);
            y4[j].z = d.z - fmaf(k4[j].z, 2.f*cur.z - prev.z - nxt.z, EPSF*cur.z);
            y4[j].w = d.w - fmaf(k4[j].w, 2.f*cur.w - prev.w - nxt.w, EPSF*cur.w);
            prev = cur;
        }
    }

    #pragma unroll
    for (int j = 0; j < 4; j++)
        *(float4*)(up + j*NS) = y4[j];
}

// ---------------------------------------------------------------------------
// Inputs (metadata order): u, alpha_base, beta_base, alpha_time_coeff,
// beta_time_coeff, channel_mixing. Output: float32 [16,8,128,128].
// Four b-group chains on four streams; coefficient precompute on the origin
// stream runs concurrently with the head k_x and is joined via event.
// ---------------------------------------------------------------------------
extern "C" void kernel_launch(void* const* d_in, const int* in_sizes, int n_in,
                              void* d_out, int out_size)
{
    (void)in_sizes; (void)n_in; (void)out_size;
    const float* u   = (const float*)d_in[0];
    const float* ab  = (const float*)d_in[1];
    const float* bb  = (const float*)d_in[2];
    const float* atc = (const float*)d_in[3];
    const float* btc = (const float*)d_in[4];
    const float* cm  = (const float*)d_in[5];

    // fork from the capture-origin stream
    cudaEventRecord(g_fork, 0);
    for (int i = 0; i < NGRP; i++)
        cudaStreamWaitEvent(g_s[i], g_fork, 0);

    // coefficient precompute on origin stream (concurrent with head k_x)
    kpre<<<(NA4 + NB4 + 255)/256, 256>>>(ab, atc, bb, btc);
    cudaEventRecord(g_pre, 0);

    for (int i = 0; i < NGRP; i++) {
        const int b0 = i * NBG;
        cudaStream_t st = g_s[i];

        // head: mix + X(alpha @ t=0) — needs only ab, independent of kpre
        k_x<0><<<NBG*NS, 256, 0, st>>>(u, nullptr, ab, cm, 0, b0);

        cudaStreamWaitEvent(st, g_pre, 0);   // coefficients ready

        for (int k = 0; k < NSTEPS; k++) {
            k_y<<<NBG*NC, 1024, 0, st>>>(k, b0);
            if (k < NSTEPS-1)
                k_x<1><<<NBG*NS, 256, 0, st>>>(nullptr, nullptr, ab, cm, k+1, b0);
            else
                k_x<2><<<NBG*NS, 256, 0, st>>>(nullptr, (float*)d_out, ab, cm, NSTEPS, b0);
        }
    }

    // join back to the capture-origin stream
    for (int i = 0; i < NGRP; i++) {
        cudaEventRecord(g_join[i], g_s[i]);
        cudaStreamWaitEvent(0, g_join[i], 0);
    }
}

// round 17
// speedup vs baseline: 1.0410x; 1.0410x over previous
#include <cuda_runtime.h>

#define NB 16
#define NBG 2        // batches per stream-group
#define NGRP 8       // stream groups (NBG*NGRP == NB)
#define NC 8
#define NS 128
#define NSTEPS 10
#define EPSF 1e-6f
#define FULLM 0xFFFFFFFFu
#define NITER 2      // proven sufficient (rel_err 7e-7)

// ping state (device global: allocation-free rule)
static __device__ float g_u[NB*NC*NS*NS];

// streams/events created once at module load (no device allocations involved)
static cudaStream_t g_s[NGRP];
static cudaEvent_t  g_fork, g_join[NGRP];
namespace {
struct StreamInit {
    StreamInit() {
        for (int i = 0; i < NGRP; i++)
            cudaStreamCreateWithFlags(&g_s[i], cudaStreamNonBlocking);
        cudaEventCreateWithFlags(&g_fork, cudaEventDisableTiming);
        for (int i = 0; i < NGRP; i++)
            cudaEventCreateWithFlags(&g_join[i], cudaEventDisableTiming);
    }
} g_streamInit;
}

// ---------------------------------------------------------------------------
// Warp-shuffle Neumann solve (2 iters); warp owns a 128-row, 4 elems/thread.
// Mirror ghosts reproduce the b=1+k boundary rows exactly.
// ---------------------------------------------------------------------------
static __device__ __forceinline__ void xsolve(float y[4], const float d[4],
                                              const float k[4], int l)
{
    #pragma unroll
    for (int it = 0; it < NITER; it++) {
        float ym1 = __shfl_up_sync(FULLM, y[3], 1);
        float yp1 = __shfl_down_sync(FULLM, y[0], 1);
        if (l == 0)  ym1 = y[0];
        if (l == 31) yp1 = y[3];
        float prev = ym1;
        #pragma unroll
        for (int e = 0; e < 4; e++) {
            float cur = y[e];
            float nxt = (e < 3) ? y[e+1] : yp1;
            float L = 2.f*cur - prev - nxt;
            y[e] = d[e] - fmaf(k[e], L, EPSF*cur);
            prev = cur;
        }
    }
}

// ---------------------------------------------------------------------------
// X-direction kernel (R9/R6/R4 config). CTA = (b, h); warp c = channel c.
// grid = NBG*NS per group; b = b0 + (blockIdx.x >> 7).
// MODE 0: mix(usrc) + X          -> g_u        (head, alpha @ t=0)
// MODE 1: X + mix + X (in place) -> g_u        (body, same alpha set twice)
// MODE 2: X                      -> uout       (tail, alpha @ t=10dt)
// ---------------------------------------------------------------------------
template<int MODE>
__global__ void __launch_bounds__(256) k_x(const float* __restrict__ usrc,
                                           float* __restrict__ uout,
                                           const float* __restrict__ ab,
                                           const float* __restrict__ atc,
                                           const float* __restrict__ cm,
                                           float t, int b0)
{
    __shared__ float sm[NC][NS];
    const int tid = threadIdx.x;
    const int c = tid >> 5;
    const int l = tid & 31;
    const int b = b0 + (blockIdx.x >> 7);
    const int h = blockIdx.x & 127;

    const size_t crow = (((size_t)c*NS + h))*NS + 4*l;
    const size_t urow = ((((size_t)b*NC + c)*NS + h))*NS + 4*l;

    float k[4];
    {
        const float4 a4 = *(const float4*)(ab + crow);
        const float4 c4 = *(const float4*)(atc + crow);
        k[0] = fminf(fmaxf(fmaf(c4.x, t, a4.x), 1e-6f), 10.f) * 0.0005f;
        k[1] = fminf(fmaxf(fmaf(c4.y, t, a4.y), 1e-6f), 10.f) * 0.0005f;
        k[2] = fminf(fmaxf(fmaf(c4.z, t, a4.z), 1e-6f), 10.f) * 0.0005f;
        k[3] = fminf(fmaxf(fmaf(c4.w, t, a4.w), 1e-6f), 10.f) * 0.0005f;
    }

    float cmr[8];
    if (MODE != 2) {
        #pragma unroll
        for (int j = 0; j < 8; j++) cmr[j] = cm[c*8 + j];
    }

    float d[4];
    {
        const float* src = (MODE == 0) ? usrc : (const float*)g_u;
        const float4 v = *(const float4*)(src + urow);
        d[0] = v.x; d[1] = v.y; d[2] = v.z; d[3] = v.w;
    }

    if (MODE == 0) {
        *(float4*)&sm[c][4*l] = make_float4(d[0], d[1], d[2], d[3]);
        __syncthreads();
        float m[4] = {0.f, 0.f, 0.f, 0.f};
        #pragma unroll
        for (int j = 0; j < 8; j++) {
            const float4 v = *(const float4*)&sm[j][4*l];
            m[0] = fmaf(cmr[j], v.x, m[0]);
            m[1] = fmaf(cmr[j], v.y, m[1]);
            m[2] = fmaf(cmr[j], v.z, m[2]);
            m[3] = fmaf(cmr[j], v.w, m[3]);
        }
        float y[4] = {m[0], m[1], m[2], m[3]};
        xsolve(y, m, k, l);
        *(float4*)((float*)g_u + urow) = make_float4(y[0], y[1], y[2], y[3]);
    } else if (MODE == 1) {
        float y[4] = {d[0], d[1], d[2], d[3]};
        xsolve(y, d, k, l);
        *(float4*)&sm[c][4*l] = make_float4(y[0], y[1], y[2], y[3]);
        __syncthreads();
        float m[4] = {0.f, 0.f, 0.f, 0.f};
        #pragma unroll
        for (int j = 0; j < 8; j++) {
            const float4 v = *(const float4*)&sm[j][4*l];
            m[0] = fmaf(cmr[j], v.x, m[0]);
            m[1] = fmaf(cmr[j], v.y, m[1]);
            m[2] = fmaf(cmr[j], v.z, m[2]);
            m[3] = fmaf(cmr[j], v.w, m[3]);
        }
        float y2[4] = {m[0], m[1], m[2], m[3]};
        xsolve(y2, m, k, l);
        *(float4*)((float*)g_u + urow) = make_float4(y2[0], y2[1], y2[2], y2[3]);
    } else {
        float y[4] = {d[0], d[1], d[2], d[3]};
        xsolve(y, d, k, l);
        *(float4*)(uout + urow) = make_float4(y[0], y[1], y[2], y[3]);
    }
}

// ---------------------------------------------------------------------------
// Y-direction kernel (R9/R6 config). CTA = (b, c, w-tile of 32); 512 threads
// as (32 w-lanes) x (16 h-segments of 8). Thread owns 8 h in registers;
// segment halos via double-buffered smem rows. In place on g_u.
// grid = NBG*NC*4 per group; b = b0 + (blockIdx.x >> 5).
// ---------------------------------------------------------------------------
__global__ void __launch_bounds__(512, 3) k_y(const float* __restrict__ bb,
                                              const float* __restrict__ btc,
                                              float t, int b0)
{
    __shared__ float sTop[NITER][16][32];
    __shared__ float sBot[NITER][16][32];
    const int wl = threadIdx.x & 31;
    const int s  = threadIdx.x >> 5;        // 0..15 segment
    const int wt = blockIdx.x & 3;
    const int c  = (blockIdx.x >> 2) & 7;
    const int b  = b0 + (blockIdx.x >> 5);
    const int w  = wt*32 + wl;
    const int h0 = s*8;

    const size_t cbase = (((size_t)c*NS + h0))*NS + w;
    const size_t ubase = ((((size_t)b*NC + c)*NS + h0))*NS + w;

    float k[8], d[8], y[8];
    #pragma unroll
    for (int j = 0; j < 8; j++) {
        const float base = bb [cbase + (size_t)j*NS];
        const float tc   = btc[cbase + (size_t)j*NS];
        k[j] = fminf(fmaxf(fmaf(tc, t, base), 1e-6f), 10.f) * 0.001f;  // *DT/DY^2
        d[j] = g_u[ubase + (size_t)j*NS];
        y[j] = d[j];
    }

    #pragma unroll
    for (int it = 0; it < NITER; it++) {
        sTop[it][s][wl] = y[0];
        sBot[it][s][wl] = y[7];
        __syncthreads();
        const float ym1 = (s == 0)  ? y[0] : sBot[it][s-1][wl];
        const float yp1 = (s == 15) ? y[7] : sTop[it][s+1][wl];
        float prev = ym1;
        #pragma unroll
        for (int j = 0; j < 8; j++) {
            const float cur = y[j];
            const float nxt = (j < 7) ? y[j+1] : yp1;
            const float L = 2.f*cur - prev - nxt;
            y[j] = d[j] - fmaf(k[j], L, EPSF*cur);
            prev = cur;
        }
    }

    #pragma unroll
    for (int j = 0; j < 8; j++)
        g_u[ubase + (size_t)j*NS] = y[j];
}

// ---------------------------------------------------------------------------
// Inputs (metadata order): u, alpha_base, beta_base, alpha_time_coeff,
// beta_time_coeff, channel_mixing. Output: float32 [16,8,128,128].
// Eight independent b-group chains on eight streams (fork/join via events so
// graph capture records the parallelism).
// ---------------------------------------------------------------------------
extern "C" void kernel_launch(void* const* d_in, const int* in_sizes, int n_in,
                              void* d_out, int out_size)
{
    (void)in_sizes; (void)n_in; (void)out_size;
    const float* u   = (const float*)d_in[0];
    const float* ab  = (const float*)d_in[1];
    const float* bb  = (const float*)d_in[2];
    const float* atc = (const float*)d_in[3];
    const float* btc = (const float*)d_in[4];
    const float* cm  = (const float*)d_in[5];

    // fork from the capture-origin (default) stream
    cudaEventRecord(g_fork, 0);
    for (int i = 0; i < NGRP; i++)
        cudaStreamWaitEvent(g_s[i], g_fork, 0);

    for (int i = 0; i < NGRP; i++) {
        const int b0 = i * NBG;
        cudaStream_t st = g_s[i];

        // head: mix + X(alpha @ t=0)
        k_x<0><<<NBG*NS, 256, 0, st>>>(u, nullptr, ab, atc, cm, 0.f, b0);

        for (int k = 0; k < NSTEPS; k++) {
            const float tB = (float)((double)k * 0.001 + 0.0005);
            k_y<<<NBG*NC*4, 512, 0, st>>>(bb, btc, tB, b0);
            const float tA = (float)((double)(k+1) * 0.001);
            if (k < NSTEPS-1)
                k_x<1><<<NBG*NS, 256, 0, st>>>(nullptr, nullptr, ab, atc, cm, tA, b0);
            else
                k_x<2><<<NBG*NS, 256, 0, st>>>(nullptr, (float*)d_out, ab, atc, cm, tA, b0);
        }
    }

    // join back to the capture-origin stream
    for (int i = 0; i < NGRP; i++) {
        cudaEventRecord(g_join[i], g_s[i]);
        cudaStreamWaitEvent(0, g_join[i], 0);
    }
}